// round 13
// baseline (speedup 1.0000x reference)
#include <cuda_runtime.h>
#include <cuda_fp16.h>
#include <cstdint>

#define H      128
#define NH     8
#define HDIM   16
#define MAXDEG 16
#define MAXN_PAD 50048      // 391 * 128, >= N

// ---------------- scratch (device globals: no allocations allowed) ----------
// Q fp32, PERMUTED: feature f = d*8+hd -> slot hd*16+d (head-contiguous).
// K fp16, PERMUTED same layout.  V fp16, ORIGINAL layout.
__device__ __align__(16) float  g_Q[MAXN_PAD * H];
__device__ __align__(16) __half g_K[MAXN_PAD * H];
__device__ __align__(16) __half g_V[MAXN_PAD * H];

// ---------------- packed f32x2 helpers --------------------------------------
__device__ __forceinline__ unsigned long long fma2(unsigned long long a,
                                                   unsigned long long b,
                                                   unsigned long long c) {
    unsigned long long d;
    asm("fma.rn.f32x2 %0, %1, %2, %3;" : "=l"(d) : "l"(a), "l"(b), "l"(c));
    return d;
}
__device__ __forceinline__ unsigned long long dup2(float x) {
    unsigned long long r;
    unsigned int xi = __float_as_uint(x);
    asm("mov.b64 %0, {%1, %1};" : "=l"(r) : "r"(xi));
    return r;
}
__device__ __forceinline__ void unpack2(unsigned long long v, float& lo, float& hi) {
    unsigned int a, b;
    asm("mov.b64 {%0, %1}, %2;" : "=r"(a), "=r"(b) : "l"(v));
    lo = __uint_as_float(a);
    hi = __uint_as_float(b);
}

// ---------------- QKV projection: C = h @ W^T + b (x scale for Q) -----------
// Exact R6/R12 mainloop (fma-pipe bound, ~94% of FFMA2 rt=3 floor). blockIdx.z:
// 0->Q fp32 perm, 1->K fp16 perm, 2->V fp16 original.
__global__ __launch_bounds__(256, 2) void qkv_gemm(
    const float* __restrict__ hmat,
    const float* __restrict__ Wq, const float* __restrict__ bq,
    const float* __restrict__ Wk, const float* __restrict__ bk,
    const float* __restrict__ Wv, const float* __restrict__ bv,
    int N)
{
    const int z = blockIdx.z;
    const float* __restrict__ W    = (z == 0) ? Wq : (z == 1) ? Wk : Wv;
    const float* __restrict__ bias = (z == 0) ? bq : (z == 1) ? bk : bv;
    const float scale = (z == 0) ? 0.25f : 1.0f;   // head_dim^-0.5 = 16^-0.5

    __shared__ __align__(16) float As[32][132];    // [k][m]
    __shared__ __align__(16) float Bs[32][132];    // [k][n]

    const int tid  = threadIdx.x;
    const int row0 = blockIdx.x * 128;
    const int sr   = tid >> 1;               // staging row 0..127
    const int sc   = (tid & 1) * 16;         // staging col base 0 or 16
    const int tx   = tid & 15;               // n-tile 0..15
    const int ty   = tid >> 4;               // m-tile 0..15
    const bool arow_ok = (row0 + sr < N);

    unsigned long long acc[8][4];
#pragma unroll
    for (int i = 0; i < 8; i++)
#pragma unroll
        for (int j = 0; j < 4; j++) acc[i][j] = 0ULL;

    // prefetch chunk 0
    float4 av[4], wv[4];
#pragma unroll
    for (int i = 0; i < 4; i++) {
        av[i] = arow_ok
            ? *reinterpret_cast<const float4*>(hmat + (size_t)(row0 + sr) * H + sc + i * 4)
            : make_float4(0.f, 0.f, 0.f, 0.f);
        wv[i] = *reinterpret_cast<const float4*>(W + (size_t)sr * H + sc + i * 4);
    }

    for (int chunk = 0; chunk < 4; chunk++) {
#pragma unroll
        for (int i = 0; i < 4; i++) {
            int k0 = sc + i * 4;
            As[k0 + 0][sr] = av[i].x; As[k0 + 1][sr] = av[i].y;
            As[k0 + 2][sr] = av[i].z; As[k0 + 3][sr] = av[i].w;
            Bs[k0 + 0][sr] = wv[i].x; Bs[k0 + 1][sr] = wv[i].y;
            Bs[k0 + 2][sr] = wv[i].z; Bs[k0 + 3][sr] = wv[i].w;
        }
        __syncthreads();

        if (chunk < 3) {
            int kk = (chunk + 1) * 32;
#pragma unroll
            for (int i = 0; i < 4; i++) {
                av[i] = arow_ok
                    ? *reinterpret_cast<const float4*>(hmat + (size_t)(row0 + sr) * H + kk + sc + i * 4)
                    : make_float4(0.f, 0.f, 0.f, 0.f);
                wv[i] = *reinterpret_cast<const float4*>(W + (size_t)sr * H + kk + sc + i * 4);
            }
        }

#pragma unroll 8
        for (int k = 0; k < 32; k++) {
            ulonglong2 b01 = *reinterpret_cast<const ulonglong2*>(&Bs[k][tx * 8]);
            ulonglong2 b23 = *reinterpret_cast<const ulonglong2*>(&Bs[k][tx * 8 + 4]);
            float4 a0 = *reinterpret_cast<const float4*>(&As[k][ty * 8]);
            float4 a1 = *reinterpret_cast<const float4*>(&As[k][ty * 8 + 4]);
            unsigned long long ad[8];
            ad[0] = dup2(a0.x); ad[1] = dup2(a0.y); ad[2] = dup2(a0.z); ad[3] = dup2(a0.w);
            ad[4] = dup2(a1.x); ad[5] = dup2(a1.y); ad[6] = dup2(a1.z); ad[7] = dup2(a1.w);
#pragma unroll
            for (int i = 0; i < 8; i++) {
                acc[i][0] = fma2(ad[i], b01.x, acc[i][0]);
                acc[i][1] = fma2(ad[i], b01.y, acc[i][1]);
                acc[i][2] = fma2(ad[i], b23.x, acc[i][2]);
                acc[i][3] = fma2(ad[i], b23.y, acc[i][3]);
            }
        }
        __syncthreads();
    }

    // epilogue: bias + scale, then per-z store (fp32 perm / fp16 perm / fp16)
    float bl[8];
#pragma unroll
    for (int u = 0; u < 8; u++) bl[u] = __ldg(bias + tx * 8 + u);

#pragma unroll
    for (int i = 0; i < 8; i++) {
        int gr = row0 + ty * 8 + i;
        if (gr >= N) continue;
        float vals[8];
#pragma unroll
        for (int j = 0; j < 4; j++) {
            float lo, hi;
            unpack2(acc[i][j], lo, hi);
            vals[2 * j]     = (lo + bl[2 * j])     * scale;
            vals[2 * j + 1] = (hi + bl[2 * j + 1]) * scale;
        }
        if (z == 0) {
            // Q fp32, permuted: c = tx*8+u -> slot (c&7)*16 + (c>>3) = u*16 + tx
            float* crow = g_Q + (size_t)gr * H;
#pragma unroll
            for (int u = 0; u < 8; u++) crow[u * 16 + tx] = vals[u];
        } else if (z == 1) {
            // K fp16, permuted
            __half* crow = g_K + (size_t)gr * H;
#pragma unroll
            for (int u = 0; u < 8; u++) crow[u * 16 + tx] = __float2half_rn(vals[u]);
        } else {
            // V fp16, original layout: 8 halves = 16B contiguous
            __half hv[8];
#pragma unroll
            for (int u = 0; u < 8; u++) hv[u] = __float2half_rn(vals[u]);
            *reinterpret_cast<uint4*>(g_V + (size_t)gr * H + tx * 8) =
                *reinterpret_cast<const uint4*>(hv);
        }
    }
}

// ---------------- fused sparse attention: one warp per node -----------------
// Score pass: lane = (h = lane&7, e2 = lane>>3); lane computes head h's full
// 16-dim dot (fp32 accumulate) for edges e2*4..e2*4+3 from head-contiguous K.
// Softmax across the 4 partner lanes of head h via shfl_xor 8,16.
// V pass: lane owns features f=4*lane..4*lane+3 -> head 4*(lane&1)+j.
__global__ __launch_bounds__(256) void attn_kernel(
    const int* __restrict__ row_ptr,
    const int* __restrict__ col_ind,
    float* __restrict__ out,
    int N)
{
    __shared__ float att[8][NH][MAXDEG];   // [local warp][head][edge]

    const int wl   = threadIdx.x >> 5;
    const int lane = threadIdx.x & 31;
    const int node = blockIdx.x * 8 + wl;
    if (node >= N) return;                 // warp-uniform; only __syncwarp below

    const int start = row_ptr[node];
    int deg = row_ptr[node + 1] - start;
    if (deg > MAXDEG) deg = MAXDEG;

    int colv = 0;
    if (lane < MAXDEG && lane < deg) colv = col_ind[start + lane];

    // ---- score pass: (head, edge-group) per lane ----
    const int h  = lane & 7;
    const int e2 = lane >> 3;              // 0..3 -> edges e2*4..e2*4+3

    // q[h]: 16 fp32 from the permuted Q row (head-contiguous)
    float qh[16];
    {
        const float4* qp = reinterpret_cast<const float4*>(
            g_Q + (size_t)node * H + h * HDIM);
        float4 t0 = __ldg(qp + 0), t1 = __ldg(qp + 1);
        float4 t2 = __ldg(qp + 2), t3 = __ldg(qp + 3);
        qh[0]=t0.x; qh[1]=t0.y; qh[2]=t0.z; qh[3]=t0.w;
        qh[4]=t1.x; qh[5]=t1.y; qh[6]=t1.z; qh[7]=t1.w;
        qh[8]=t2.x; qh[9]=t2.y; qh[10]=t2.z; qh[11]=t2.w;
        qh[12]=t3.x; qh[13]=t3.y; qh[14]=t3.z; qh[15]=t3.w;
    }

    const float NEG_INF = __int_as_float(0xff800000);
    float sc4[4];
#pragma unroll
    for (int i = 0; i < 4; i++) {
        int e = e2 * 4 + i;
        int col = __shfl_sync(0xffffffffu, colv, e);
        const uint4* kp = reinterpret_cast<const uint4*>(
            g_K + (size_t)col * H + h * HDIM);
        uint4 ka = __ldg(kp + 0);
        uint4 kb = __ldg(kp + 1);
        float p = 0.0f;
        float2 f;
        f = __half22float2(*reinterpret_cast<const __half2*>(&ka.x)); p += qh[0]*f.x + qh[1]*f.y;
        f = __half22float2(*reinterpret_cast<const __half2*>(&ka.y)); p += qh[2]*f.x + qh[3]*f.y;
        f = __half22float2(*reinterpret_cast<const __half2*>(&ka.z)); p += qh[4]*f.x + qh[5]*f.y;
        f = __half22float2(*reinterpret_cast<const __half2*>(&ka.w)); p += qh[6]*f.x + qh[7]*f.y;
        f = __half22float2(*reinterpret_cast<const __half2*>(&kb.x)); p += qh[8]*f.x + qh[9]*f.y;
        f = __half22float2(*reinterpret_cast<const __half2*>(&kb.y)); p += qh[10]*f.x + qh[11]*f.y;
        f = __half22float2(*reinterpret_cast<const __half2*>(&kb.z)); p += qh[12]*f.x + qh[13]*f.y;
        f = __half22float2(*reinterpret_cast<const __half2*>(&kb.w)); p += qh[14]*f.x + qh[15]*f.y;
        sc4[i] = (e < deg) ? p : NEG_INF;
    }

    // softmax over 16 edges of head h: 4 local + partner lanes (xor 8, 16)
    float m = fmaxf(fmaxf(sc4[0], sc4[1]), fmaxf(sc4[2], sc4[3]));
    m = fmaxf(m, __shfl_xor_sync(0xffffffffu, m, 8));
    m = fmaxf(m, __shfl_xor_sync(0xffffffffu, m, 16));
    float s = 0.0f;
#pragma unroll
    for (int i = 0; i < 4; i++) { float x = __expf(sc4[i] - m); sc4[i] = x; s += x; }
    s += __shfl_xor_sync(0xffffffffu, s, 8);
    s += __shfl_xor_sync(0xffffffffu, s, 16);
    float r = __frcp_rn(s);
#pragma unroll
    for (int i = 0; i < 4; i++) sc4[i] *= r;

    // store lane's 4 weights: att[wl][h][e2*4..e2*4+3] (contiguous, one STS.128)
    *reinterpret_cast<float4*>(&att[wl][h][e2 * 4]) =
        make_float4(sc4[0], sc4[1], sc4[2], sc4[3]);
    __syncwarp();

    // ---- bspmm: coalesced fp16 V rows; weights as float4 (4 edges/LDS.128) ----
    const int base = (lane & 1) * 4;
    float4 acc = make_float4(0.f, 0.f, 0.f, 0.f);
#pragma unroll
    for (int e0 = 0; e0 < MAXDEG; e0 += 4) {
        float4 a0 = *reinterpret_cast<const float4*>(&att[wl][base + 0][e0]);
        float4 a1 = *reinterpret_cast<const float4*>(&att[wl][base + 1][e0]);
        float4 a2 = *reinterpret_cast<const float4*>(&att[wl][base + 2][e0]);
        float4 a3 = *reinterpret_cast<const float4*>(&att[wl][base + 3][e0]);
        const float* w0 = reinterpret_cast<const float*>(&a0);
        const float* w1 = reinterpret_cast<const float*>(&a1);
        const float* w2 = reinterpret_cast<const float*>(&a2);
        const float* w3 = reinterpret_cast<const float*>(&a3);
#pragma unroll
        for (int u = 0; u < 4; u++) {
            int col = __shfl_sync(0xffffffffu, colv, e0 + u);
            uint2 vr = __ldg(reinterpret_cast<const uint2*>(g_V + (size_t)col * H) + lane);
            float2 v01 = __half22float2(*reinterpret_cast<const __half2*>(&vr.x));
            float2 v23 = __half22float2(*reinterpret_cast<const __half2*>(&vr.y));
            acc.x += w0[u] * v01.x;
            acc.y += w1[u] * v01.y;
            acc.z += w2[u] * v23.x;
            acc.w += w3[u] * v23.y;
        }
    }
    *reinterpret_cast<float4*>(out + (size_t)node * H + lane * 4) = acc;
}

// ---------------- launch -----------------------------------------------------
extern "C" void kernel_launch(void* const* d_in, const int* in_sizes, int n_in,
                              void* d_out, int out_size) {
    const float* h   = (const float*)d_in[0];
    const float* Wq  = (const float*)d_in[1];
    const float* bq  = (const float*)d_in[2];
    const float* Wk  = (const float*)d_in[3];
    const float* bk  = (const float*)d_in[4];
    const float* Wv  = (const float*)d_in[5];
    const float* bv  = (const float*)d_in[6];
    const int* row_ptr = (const int*)d_in[7];
    const int* col_ind = (const int*)d_in[8];
    float* out = (float*)d_out;

    const int N = in_sizes[0] / H;

    dim3 ggrid((N + 127) / 128, 1, 3);
    qkv_gemm<<<ggrid, 256>>>(h, Wq, bq, Wk, bk, Wv, bv, N);

    const int ablocks = (N + 7) / 8;       // 8 nodes (warps) per 256-thread block
    attn_kernel<<<ablocks, 256>>>(row_ptr, col_ind, out, N);
}

// round 14
// speedup vs baseline: 1.0123x; 1.0123x over previous
#include <cuda_runtime.h>
#include <cuda_fp16.h>
#include <cstdint>

#define H      128
#define NH     8
#define HDIM   16
#define MAXDEG 16
#define MAXN_PAD 50048      // 391 * 128, >= N

// ---------------- scratch (device globals: no allocations allowed) ----------
// Q fp32, PERMUTED: feature f = d*8+hd -> slot hd*16+d (head-contiguous).
// K fp16, PERMUTED same layout.  V fp16, ORIGINAL layout.
__device__ __align__(16) float  g_Q[MAXN_PAD * H];
__device__ __align__(16) __half g_K[MAXN_PAD * H];
__device__ __align__(16) __half g_V[MAXN_PAD * H];

// ---------------- packed f32x2 helpers --------------------------------------
__device__ __forceinline__ unsigned long long fma2(unsigned long long a,
                                                   unsigned long long b,
                                                   unsigned long long c) {
    unsigned long long d;
    asm("fma.rn.f32x2 %0, %1, %2, %3;" : "=l"(d) : "l"(a), "l"(b), "l"(c));
    return d;
}
__device__ __forceinline__ unsigned long long dup2(float x) {
    unsigned long long r;
    unsigned int xi = __float_as_uint(x);
    asm("mov.b64 %0, {%1, %1};" : "=l"(r) : "r"(xi));
    return r;
}
__device__ __forceinline__ void unpack2(unsigned long long v, float& lo, float& hi) {
    unsigned int a, b;
    asm("mov.b64 {%0, %1}, %2;" : "=r"(a), "=r"(b) : "l"(v));
    lo = __uint_as_float(a);
    hi = __uint_as_float(b);
}
__device__ __forceinline__ uint32_t smem_u32(const void* p) {
    uint32_t a;
    asm("{ .reg .u64 t; cvta.to.shared.u64 t, %1; cvt.u32.u64 %0, t; }"
        : "=r"(a) : "l"(p));
    return a;
}
__device__ __forceinline__ void ldmatrix_x4(uint32_t& r0, uint32_t& r1,
                                            uint32_t& r2, uint32_t& r3,
                                            uint32_t addr) {
    asm volatile("ldmatrix.sync.aligned.m8n8.x4.shared.b16 {%0,%1,%2,%3}, [%4];"
                 : "=r"(r0), "=r"(r1), "=r"(r2), "=r"(r3) : "r"(addr));
}
__device__ __forceinline__ void mma_f16(float c[4], uint32_t a0, uint32_t a1,
                                        uint32_t a2, uint32_t a3,
                                        uint32_t b0, uint32_t b1) {
    asm volatile(
        "mma.sync.aligned.m16n8k16.row.col.f32.f16.f16.f32 "
        "{%0,%1,%2,%3},{%4,%5,%6,%7},{%8,%9},{%0,%1,%2,%3};"
        : "+f"(c[0]), "+f"(c[1]), "+f"(c[2]), "+f"(c[3])
        : "r"(a0), "r"(a1), "r"(a2), "r"(a3), "r"(b0), "r"(b1));
}

// ---------------- Q projection: fp32 FFMA2 (proven R6/R12 kernel, z=0) ------
__global__ __launch_bounds__(256, 2) void qkv_gemm(
    const float* __restrict__ hmat,
    const float* __restrict__ Wq, const float* __restrict__ bq,
    int N)
{
    const float* __restrict__ W    = Wq;
    const float* __restrict__ bias = bq;
    const float scale = 0.25f;               // head_dim^-0.5 = 16^-0.5

    __shared__ __align__(16) float As[32][132];    // [k][m]
    __shared__ __align__(16) float Bs[32][132];    // [k][n]

    const int tid  = threadIdx.x;
    const int row0 = blockIdx.x * 128;
    const int sr   = tid >> 1;
    const int sc   = (tid & 1) * 16;
    const int tx   = tid & 15;
    const int ty   = tid >> 4;
    const bool arow_ok = (row0 + sr < N);

    unsigned long long acc[8][4];
#pragma unroll
    for (int i = 0; i < 8; i++)
#pragma unroll
        for (int j = 0; j < 4; j++) acc[i][j] = 0ULL;

    float4 av[4], wv[4];
#pragma unroll
    for (int i = 0; i < 4; i++) {
        av[i] = arow_ok
            ? *reinterpret_cast<const float4*>(hmat + (size_t)(row0 + sr) * H + sc + i * 4)
            : make_float4(0.f, 0.f, 0.f, 0.f);
        wv[i] = *reinterpret_cast<const float4*>(W + (size_t)sr * H + sc + i * 4);
    }

    for (int chunk = 0; chunk < 4; chunk++) {
#pragma unroll
        for (int i = 0; i < 4; i++) {
            int k0 = sc + i * 4;
            As[k0 + 0][sr] = av[i].x; As[k0 + 1][sr] = av[i].y;
            As[k0 + 2][sr] = av[i].z; As[k0 + 3][sr] = av[i].w;
            Bs[k0 + 0][sr] = wv[i].x; Bs[k0 + 1][sr] = wv[i].y;
            Bs[k0 + 2][sr] = wv[i].z; Bs[k0 + 3][sr] = wv[i].w;
        }
        __syncthreads();

        if (chunk < 3) {
            int kk = (chunk + 1) * 32;
#pragma unroll
            for (int i = 0; i < 4; i++) {
                av[i] = arow_ok
                    ? *reinterpret_cast<const float4*>(hmat + (size_t)(row0 + sr) * H + kk + sc + i * 4)
                    : make_float4(0.f, 0.f, 0.f, 0.f);
                wv[i] = *reinterpret_cast<const float4*>(W + (size_t)sr * H + kk + sc + i * 4);
            }
        }

#pragma unroll 8
        for (int k = 0; k < 32; k++) {
            ulonglong2 b01 = *reinterpret_cast<const ulonglong2*>(&Bs[k][tx * 8]);
            ulonglong2 b23 = *reinterpret_cast<const ulonglong2*>(&Bs[k][tx * 8 + 4]);
            float4 a0 = *reinterpret_cast<const float4*>(&As[k][ty * 8]);
            float4 a1 = *reinterpret_cast<const float4*>(&As[k][ty * 8 + 4]);
            unsigned long long ad[8];
            ad[0] = dup2(a0.x); ad[1] = dup2(a0.y); ad[2] = dup2(a0.z); ad[3] = dup2(a0.w);
            ad[4] = dup2(a1.x); ad[5] = dup2(a1.y); ad[6] = dup2(a1.z); ad[7] = dup2(a1.w);
#pragma unroll
            for (int i = 0; i < 8; i++) {
                acc[i][0] = fma2(ad[i], b01.x, acc[i][0]);
                acc[i][1] = fma2(ad[i], b01.y, acc[i][1]);
                acc[i][2] = fma2(ad[i], b23.x, acc[i][2]);
                acc[i][3] = fma2(ad[i], b23.y, acc[i][3]);
            }
        }
        __syncthreads();
    }

    float bl[8];
#pragma unroll
    for (int u = 0; u < 8; u++) bl[u] = __ldg(bias + tx * 8 + u);

#pragma unroll
    for (int i = 0; i < 8; i++) {
        int gr = row0 + ty * 8 + i;
        if (gr >= N) continue;
        float vals[8];
#pragma unroll
        for (int j = 0; j < 4; j++) {
            float lo, hi;
            unpack2(acc[i][j], lo, hi);
            vals[2 * j]     = (lo + bl[2 * j])     * scale;
            vals[2 * j + 1] = (hi + bl[2 * j + 1]) * scale;
        }
        // Q fp32, permuted: c = tx*8+u -> slot (c&7)*16 + (c>>3) = u*16 + tx
        float* crow = g_Q + (size_t)gr * H;
#pragma unroll
        for (int u = 0; u < 8; u++) crow[u * 16 + tx] = vals[u];
    }
}

// ---------------- K,V projection: fp16 HMMA m16n8k16 ------------------------
// blockIdx.z: 0 -> K (fp16, permuted), 1 -> V (fp16, original).
// Block tile 128x128, full K=128 staged fp16 in dynamic smem (row pitch 136
// halves -> ldmatrix conflict-free). Warp tile 32m x 64n: 2mt x 8nt x 8k.
#define HP 136                                  // half pitch per smem row
#define AB_BYTES (128 * HP * 2)                 // 34816
#define KV_SMEM  (2 * AB_BYTES)                 // 69632

__global__ __launch_bounds__(256) void kv_gemm_f16(
    const float* __restrict__ hmat,
    const float* __restrict__ Wk, const float* __restrict__ bk,
    const float* __restrict__ Wv, const float* __restrict__ bv,
    int N)
{
    const int z = blockIdx.z;                   // 0 -> K, 1 -> V
    const float* __restrict__ W    = (z == 0) ? Wk : Wv;
    const float* __restrict__ bias = (z == 0) ? bk : bv;

    extern __shared__ __align__(16) char dsm[];
    __half* As = reinterpret_cast<__half*>(dsm);             // [128][HP] (m,k)
    __half* Bs = reinterpret_cast<__half*>(dsm + AB_BYTES);  // [128][HP] (n,k)

    const int tid  = threadIdx.x;
    const int row0 = blockIdx.x * 128;
    const int warp = tid >> 5;
    const int lane = tid & 31;
    const int wm   = (warp & 3) * 32;
    const int wn   = (warp >> 2) * 64;
    const int group = lane >> 2;
    const int tg    = lane & 3;

    // ---- stage A (h rows) and B (W rows) as fp16, 64 elems per thread ----
    {
        const int r  = tid >> 1;
        const int cb = (tid & 1) * 64;
        __half2 ah[32], wh[32];
        const bool ok = (row0 + r < N);
#pragma unroll
        for (int i = 0; i < 16; i++) {
            float4 a = ok
                ? *reinterpret_cast<const float4*>(hmat + (size_t)(row0 + r) * H + cb + i * 4)
                : make_float4(0.f, 0.f, 0.f, 0.f);
            float4 w = *reinterpret_cast<const float4*>(W + (size_t)r * H + cb + i * 4);
            ah[2 * i]     = __floats2half2_rn(a.x, a.y);
            ah[2 * i + 1] = __floats2half2_rn(a.z, a.w);
            wh[2 * i]     = __floats2half2_rn(w.x, w.y);
            wh[2 * i + 1] = __floats2half2_rn(w.z, w.w);
        }
#pragma unroll
        for (int i = 0; i < 8; i++) {
            *reinterpret_cast<uint4*>(As + r * HP + cb + i * 8) =
                reinterpret_cast<const uint4*>(ah)[i];
            *reinterpret_cast<uint4*>(Bs + r * HP + cb + i * 8) =
                reinterpret_cast<const uint4*>(wh)[i];
        }
    }
    __syncthreads();

    // ---- mainloop: ldmatrix fragments + HMMA ----
    float acc[2][8][4];
#pragma unroll
    for (int mt = 0; mt < 2; mt++)
#pragma unroll
        for (int nt = 0; nt < 8; nt++)
#pragma unroll
            for (int j = 0; j < 4; j++) acc[mt][nt][j] = 0.0f;

    const uint32_t baseA = smem_u32(As);
    const uint32_t baseB = smem_u32(Bs);
    // A x4 lane addressing: row = m0 + (lane&15), col = k0 + (lane>>4)*8
    const uint32_t addrA = baseA + ((wm + (lane & 15)) * HP + (lane >> 4) * 8) * 2;
    // B x4 over nt-pair: row = n0 + (lane&7) + (lane>>4)*8, col = k0 + ((lane>>3)&1)*8
    const uint32_t addrB = baseB + ((wn + (lane & 7) + (lane >> 4) * 8) * HP
                                    + ((lane >> 3) & 1) * 8) * 2;

#pragma unroll
    for (int ks = 0; ks < 8; ks++) {
        const uint32_t koff = ks * 32;          // 16 halves = 32 bytes
        uint32_t afr[2][4];
#pragma unroll
        for (int mt = 0; mt < 2; mt++)
            ldmatrix_x4(afr[mt][0], afr[mt][1], afr[mt][2], afr[mt][3],
                        addrA + mt * 16 * (HP * 2) + koff);
#pragma unroll
        for (int ntp = 0; ntp < 4; ntp++) {
            uint32_t b00, b01, b10, b11;        // frags for nt=2ntp, 2ntp+1
            ldmatrix_x4(b00, b01, b10, b11, addrB + ntp * 16 * (HP * 2) + koff);
#pragma unroll
            for (int mt = 0; mt < 2; mt++) {
                mma_f16(acc[mt][2 * ntp],     afr[mt][0], afr[mt][1],
                        afr[mt][2], afr[mt][3], b00, b01);
                mma_f16(acc[mt][2 * ntp + 1], afr[mt][0], afr[mt][1],
                        afr[mt][2], afr[mt][3], b10, b11);
            }
        }
    }

    // ---- epilogue: bias, store fp16 (K permuted / V original) ----
#pragma unroll
    for (int nt = 0; nt < 8; nt++) {
        const int c0 = wn + nt * 8 + 2 * tg;
        const int c1 = c0 + 1;
        const float b0 = __ldg(bias + c0);
        const float b1 = __ldg(bias + c1);
        const int p0 = (c0 & 7) * HDIM + (c0 >> 3);   // permuted slot
        const int p1 = (c1 & 7) * HDIM + (c1 >> 3);
#pragma unroll
        for (int mt = 0; mt < 2; mt++) {
            const int r0 = row0 + wm + mt * 16 + group;
            const int r1 = r0 + 8;
            if (r0 < N) {
                if (z == 0) {
                    g_K[(size_t)r0 * H + p0] = __float2half_rn(acc[mt][nt][0] + b0);
                    g_K[(size_t)r0 * H + p1] = __float2half_rn(acc[mt][nt][1] + b1);
                } else {
                    *reinterpret_cast<__half2*>(g_V + (size_t)r0 * H + c0) =
                        __floats2half2_rn(acc[mt][nt][0] + b0, acc[mt][nt][1] + b1);
                }
            }
            if (r1 < N) {
                if (z == 0) {
                    g_K[(size_t)r1 * H + p0] = __float2half_rn(acc[mt][nt][2] + b0);
                    g_K[(size_t)r1 * H + p1] = __float2half_rn(acc[mt][nt][3] + b1);
                } else {
                    *reinterpret_cast<__half2*>(g_V + (size_t)r1 * H + c0) =
                        __floats2half2_rn(acc[mt][nt][2] + b0, acc[mt][nt][3] + b1);
                }
            }
        }
    }
}

// ---------------- fused sparse attention (exact R12: 46.2us measured) -------
__global__ __launch_bounds__(256) void attn_kernel(
    const int* __restrict__ row_ptr,
    const int* __restrict__ col_ind,
    float* __restrict__ out,
    int N)
{
    __shared__ float att[8][NH][MAXDEG];   // [local warp][head][edge]

    const int wl   = threadIdx.x >> 5;
    const int lane = threadIdx.x & 31;
    const int node = blockIdx.x * 8 + wl;
    if (node >= N) return;

    const int start = row_ptr[node];
    int deg = row_ptr[node + 1] - start;
    if (deg > MAXDEG) deg = MAXDEG;

    int colv = 0;
    if (lane < MAXDEG && lane < deg) colv = col_ind[start + lane];

    const float4 q4 = *reinterpret_cast<const float4*>(g_Q + (size_t)node * H + lane * 4);

    const float NEG_INF = __int_as_float(0xff800000);
    float sc[MAXDEG];
#pragma unroll
    for (int e = 0; e < MAXDEG; e++) {
        int col = __shfl_sync(0xffffffffu, colv, e);
        uint2 kr = __ldg(reinterpret_cast<const uint2*>(g_K + (size_t)col * H) + lane);
        float2 k01 = __half22float2(*reinterpret_cast<const __half2*>(&kr.x));
        float2 k23 = __half22float2(*reinterpret_cast<const __half2*>(&kr.y));
        float p = q4.x * k01.x + q4.y * k01.y + q4.z * k23.x + q4.w * k23.y;
        p += __shfl_xor_sync(0xffffffffu, p, 1);
        p += __shfl_xor_sync(0xffffffffu, p, 2);   // quad = 16 d's of head lane>>2
        sc[e] = (e < deg) ? p : NEG_INF;
    }

    float m = NEG_INF;
#pragma unroll
    for (int e = 0; e < MAXDEG; e++) m = fmaxf(m, sc[e]);
    float s = 0.0f;
#pragma unroll
    for (int e = 0; e < MAXDEG; e++) { float x = __expf(sc[e] - m); sc[e] = x; s += x; }
    float r = __frcp_rn(s);
#pragma unroll
    for (int e = 0; e < MAXDEG; e++) sc[e] *= r;

    {
        int hd = lane >> 2;
        int e0 = (lane & 3) * 4;
        *reinterpret_cast<float4*>(&att[wl][hd][e0]) =
            make_float4(sc[e0], sc[e0 + 1], sc[e0 + 2], sc[e0 + 3]);
    }
    __syncwarp();

    const int base = (lane & 1) * 4;
    float4 acc = make_float4(0.f, 0.f, 0.f, 0.f);
#pragma unroll
    for (int e0 = 0; e0 < MAXDEG; e0 += 4) {
        float4 a0 = *reinterpret_cast<const float4*>(&att[wl][base + 0][e0]);
        float4 a1 = *reinterpret_cast<const float4*>(&att[wl][base + 1][e0]);
        float4 a2 = *reinterpret_cast<const float4*>(&att[wl][base + 2][e0]);
        float4 a3 = *reinterpret_cast<const float4*>(&att[wl][base + 3][e0]);
        const float* w0 = reinterpret_cast<const float*>(&a0);
        const float* w1 = reinterpret_cast<const float*>(&a1);
        const float* w2 = reinterpret_cast<const float*>(&a2);
        const float* w3 = reinterpret_cast<const float*>(&a3);
#pragma unroll
        for (int u = 0; u < 4; u++) {
            int col = __shfl_sync(0xffffffffu, colv, e0 + u);
            uint2 vr = __ldg(reinterpret_cast<const uint2*>(g_V + (size_t)col * H) + lane);
            float2 v01 = __half22float2(*reinterpret_cast<const __half2*>(&vr.x));
            float2 v23 = __half22float2(*reinterpret_cast<const __half2*>(&vr.y));
            acc.x += w0[u] * v01.x;
            acc.y += w1[u] * v01.y;
            acc.z += w2[u] * v23.x;
            acc.w += w3[u] * v23.y;
        }
    }
    *reinterpret_cast<float4*>(out + (size_t)node * H + lane * 4) = acc;
}

// ---------------- launch -----------------------------------------------------
extern "C" void kernel_launch(void* const* d_in, const int* in_sizes, int n_in,
                              void* d_out, int out_size) {
    const float* h   = (const float*)d_in[0];
    const float* Wq  = (const float*)d_in[1];
    const float* bq  = (const float*)d_in[2];
    const float* Wk  = (const float*)d_in[3];
    const float* bk  = (const float*)d_in[4];
    const float* Wv  = (const float*)d_in[5];
    const float* bv  = (const float*)d_in[6];
    const int* row_ptr = (const int*)d_in[7];
    const int* col_ind = (const int*)d_in[8];
    float* out = (float*)d_out;

    const int N = in_sizes[0] / H;
    const int gblocks = (N + 127) / 128;

    static bool attr_set = false;
    if (!attr_set) {
        cudaFuncSetAttribute(kv_gemm_f16,
                             cudaFuncAttributeMaxDynamicSharedMemorySize, KV_SMEM);
        attr_set = true;
    }

    // Q: fp32 FFMA2 (exact);  K,V: fp16 HMMA tensor path
    qkv_gemm<<<gblocks, 256>>>(h, Wq, bq, N);
    kv_gemm_f16<<<dim3(gblocks, 1, 2), 256, KV_SMEM>>>(h, Wk, bk, Wv, bv, N);

    const int ablocks = (N + 7) / 8;
    attn_kernel<<<ablocks, 256>>>(row_ptr, col_ind, out, N);
}

// round 15
// speedup vs baseline: 1.0677x; 1.0548x over previous
#include <cuda_runtime.h>
#include <cuda_fp16.h>
#include <cstdint>

#define H      128
#define NH     8
#define HDIM   16
#define MAXDEG 16
#define MAXN_PAD 50048      // 391 * 128, >= N

// ---------------- scratch (device globals: no allocations allowed) ----------
// Q fp32, PERMUTED: feature f = d*8+hd -> slot hd*16+d (head-contiguous).
// K fp16, PERMUTED same layout.  V fp16, ORIGINAL layout.
__device__ __align__(16) float  g_Q[MAXN_PAD * H];
__device__ __align__(16) __half g_K[MAXN_PAD * H];
__device__ __align__(16) __half g_V[MAXN_PAD * H];

// ---------------- helpers ----------------------------------------------------
__device__ __forceinline__ unsigned long long fma2(unsigned long long a,
                                                   unsigned long long b,
                                                   unsigned long long c) {
    unsigned long long d;
    asm("fma.rn.f32x2 %0, %1, %2, %3;" : "=l"(d) : "l"(a), "l"(b), "l"(c));
    return d;
}
__device__ __forceinline__ unsigned long long dup2(float x) {
    unsigned long long r;
    unsigned int xi = __float_as_uint(x);
    asm("mov.b64 %0, {%1, %1};" : "=l"(r) : "r"(xi));
    return r;
}
__device__ __forceinline__ void unpack2(unsigned long long v, float& lo, float& hi) {
    unsigned int a, b;
    asm("mov.b64 {%0, %1}, %2;" : "=r"(a), "=r"(b) : "l"(v));
    lo = __uint_as_float(a);
    hi = __uint_as_float(b);
}
__device__ __forceinline__ uint32_t smem_u32(const void* p) {
    uint32_t a;
    asm("{ .reg .u64 t; cvta.to.shared.u64 t, %1; cvt.u32.u64 %0, t; }"
        : "=r"(a) : "l"(p));
    return a;
}
__device__ __forceinline__ void ldmatrix_x4(uint32_t& r0, uint32_t& r1,
                                            uint32_t& r2, uint32_t& r3,
                                            uint32_t addr) {
    asm volatile("ldmatrix.sync.aligned.m8n8.x4.shared.b16 {%0,%1,%2,%3}, [%4];"
                 : "=r"(r0), "=r"(r1), "=r"(r2), "=r"(r3) : "r"(addr));
}
__device__ __forceinline__ void mma_f16(float c[4], uint32_t a0, uint32_t a1,
                                        uint32_t a2, uint32_t a3,
                                        uint32_t b0, uint32_t b1) {
    asm volatile(
        "mma.sync.aligned.m16n8k16.row.col.f32.f16.f16.f32 "
        "{%0,%1,%2,%3},{%4,%5,%6,%7},{%8,%9},{%0,%1,%2,%3};"
        : "+f"(c[0]), "+f"(c[1]), "+f"(c[2]), "+f"(c[3])
        : "r"(a0), "r"(a1), "r"(a2), "r"(a3), "r"(b0), "r"(b1));
}

// smem sizes
#define HP 136                                  // half pitch (HMMA staging)
#define AB_BYTES (128 * HP * 2)                 // 34816
#define PROJ_SMEM (2 * AB_BYTES)                // 69632 (covers FFMA's 33792 too)

// ---------------- FFMA2 fp32 Q path (proven R6/R12 mainloop) ----------------
__device__ __forceinline__ void q_path_ffma(
    char* dsm, const float* __restrict__ hmat,
    const float* __restrict__ W, const float* __restrict__ bias, int N)
{
    float (*As)[132] = reinterpret_cast<float(*)[132]>(dsm);
    float (*Bs)[132] = reinterpret_cast<float(*)[132]>(dsm + 32 * 132 * 4);
    const float scale = 0.25f;               // head_dim^-0.5 = 16^-0.5

    const int tid  = threadIdx.x;
    const int row0 = blockIdx.x * 128;
    const int sr   = tid >> 1;
    const int sc   = (tid & 1) * 16;
    const int tx   = tid & 15;
    const int ty   = tid >> 4;
    const bool arow_ok = (row0 + sr < N);

    unsigned long long acc[8][4];
#pragma unroll
    for (int i = 0; i < 8; i++)
#pragma unroll
        for (int j = 0; j < 4; j++) acc[i][j] = 0ULL;

    float4 av[4], wv[4];
#pragma unroll
    for (int i = 0; i < 4; i++) {
        av[i] = arow_ok
            ? *reinterpret_cast<const float4*>(hmat + (size_t)(row0 + sr) * H + sc + i * 4)
            : make_float4(0.f, 0.f, 0.f, 0.f);
        wv[i] = *reinterpret_cast<const float4*>(W + (size_t)sr * H + sc + i * 4);
    }

    for (int chunk = 0; chunk < 4; chunk++) {
#pragma unroll
        for (int i = 0; i < 4; i++) {
            int k0 = sc + i * 4;
            As[k0 + 0][sr] = av[i].x; As[k0 + 1][sr] = av[i].y;
            As[k0 + 2][sr] = av[i].z; As[k0 + 3][sr] = av[i].w;
            Bs[k0 + 0][sr] = wv[i].x; Bs[k0 + 1][sr] = wv[i].y;
            Bs[k0 + 2][sr] = wv[i].z; Bs[k0 + 3][sr] = wv[i].w;
        }
        __syncthreads();

        if (chunk < 3) {
            int kk = (chunk + 1) * 32;
#pragma unroll
            for (int i = 0; i < 4; i++) {
                av[i] = arow_ok
                    ? *reinterpret_cast<const float4*>(hmat + (size_t)(row0 + sr) * H + kk + sc + i * 4)
                    : make_float4(0.f, 0.f, 0.f, 0.f);
                wv[i] = *reinterpret_cast<const float4*>(W + (size_t)sr * H + kk + sc + i * 4);
            }
        }

#pragma unroll 8
        for (int k = 0; k < 32; k++) {
            ulonglong2 b01 = *reinterpret_cast<const ulonglong2*>(&Bs[k][tx * 8]);
            ulonglong2 b23 = *reinterpret_cast<const ulonglong2*>(&Bs[k][tx * 8 + 4]);
            float4 a0 = *reinterpret_cast<const float4*>(&As[k][ty * 8]);
            float4 a1 = *reinterpret_cast<const float4*>(&As[k][ty * 8 + 4]);
            unsigned long long ad[8];
            ad[0] = dup2(a0.x); ad[1] = dup2(a0.y); ad[2] = dup2(a0.z); ad[3] = dup2(a0.w);
            ad[4] = dup2(a1.x); ad[5] = dup2(a1.y); ad[6] = dup2(a1.z); ad[7] = dup2(a1.w);
#pragma unroll
            for (int i = 0; i < 8; i++) {
                acc[i][0] = fma2(ad[i], b01.x, acc[i][0]);
                acc[i][1] = fma2(ad[i], b01.y, acc[i][1]);
                acc[i][2] = fma2(ad[i], b23.x, acc[i][2]);
                acc[i][3] = fma2(ad[i], b23.y, acc[i][3]);
            }
        }
        __syncthreads();
    }

    float bl[8];
#pragma unroll
    for (int u = 0; u < 8; u++) bl[u] = __ldg(bias + tx * 8 + u);

#pragma unroll
    for (int i = 0; i < 8; i++) {
        int gr = row0 + ty * 8 + i;
        if (gr >= N) continue;
        float vals[8];
#pragma unroll
        for (int j = 0; j < 4; j++) {
            float lo, hi;
            unpack2(acc[i][j], lo, hi);
            vals[2 * j]     = (lo + bl[2 * j])     * scale;
            vals[2 * j + 1] = (hi + bl[2 * j + 1]) * scale;
        }
        // Q fp32, permuted: c = tx*8+u -> slot (c&7)*16 + (c>>3) = u*16 + tx
        float* crow = g_Q + (size_t)gr * H;
#pragma unroll
        for (int u = 0; u < 8; u++) crow[u * 16 + tx] = vals[u];
    }
}

// ---------------- HMMA fp16 K/V path (validated R14) ------------------------
__device__ __forceinline__ void kv_path_hmma(
    char* dsm, const float* __restrict__ hmat,
    const float* __restrict__ W, const float* __restrict__ bias,
    int N, int z /* 1 -> K permuted, 2 -> V original */)
{
    __half* As = reinterpret_cast<__half*>(dsm);             // [128][HP] (m,k)
    __half* Bs = reinterpret_cast<__half*>(dsm + AB_BYTES);  // [128][HP] (n,k)

    const int tid  = threadIdx.x;
    const int row0 = blockIdx.x * 128;
    const int warp = tid >> 5;
    const int lane = tid & 31;
    const int wm   = (warp & 3) * 32;
    const int wn   = (warp >> 2) * 64;
    const int group = lane >> 2;
    const int tg    = lane & 3;

    // stage A (h rows) and B (W rows) as fp16, 64 elems per thread
    {
        const int r  = tid >> 1;
        const int cb = (tid & 1) * 64;
        __half2 ah[32], wh[32];
        const bool ok = (row0 + r < N);
#pragma unroll
        for (int i = 0; i < 16; i++) {
            float4 a = ok
                ? *reinterpret_cast<const float4*>(hmat + (size_t)(row0 + r) * H + cb + i * 4)
                : make_float4(0.f, 0.f, 0.f, 0.f);
            float4 w = *reinterpret_cast<const float4*>(W + (size_t)r * H + cb + i * 4);
            ah[2 * i]     = __floats2half2_rn(a.x, a.y);
            ah[2 * i + 1] = __floats2half2_rn(a.z, a.w);
            wh[2 * i]     = __floats2half2_rn(w.x, w.y);
            wh[2 * i + 1] = __floats2half2_rn(w.z, w.w);
        }
#pragma unroll
        for (int i = 0; i < 8; i++) {
            *reinterpret_cast<uint4*>(As + r * HP + cb + i * 8) =
                reinterpret_cast<const uint4*>(ah)[i];
            *reinterpret_cast<uint4*>(Bs + r * HP + cb + i * 8) =
                reinterpret_cast<const uint4*>(wh)[i];
        }
    }
    __syncthreads();

    float acc[2][8][4];
#pragma unroll
    for (int mt = 0; mt < 2; mt++)
#pragma unroll
        for (int nt = 0; nt < 8; nt++)
#pragma unroll
            for (int j = 0; j < 4; j++) acc[mt][nt][j] = 0.0f;

    const uint32_t baseA = smem_u32(As);
    const uint32_t baseB = smem_u32(Bs);
    const uint32_t addrA = baseA + ((wm + (lane & 15)) * HP + (lane >> 4) * 8) * 2;
    const uint32_t addrB = baseB + ((wn + (lane & 7) + (lane >> 4) * 8) * HP
                                    + ((lane >> 3) & 1) * 8) * 2;

#pragma unroll
    for (int ks = 0; ks < 8; ks++) {
        const uint32_t koff = ks * 32;          // 16 halves = 32 bytes
        uint32_t afr[2][4];
#pragma unroll
        for (int mt = 0; mt < 2; mt++)
            ldmatrix_x4(afr[mt][0], afr[mt][1], afr[mt][2], afr[mt][3],
                        addrA + mt * 16 * (HP * 2) + koff);
#pragma unroll
        for (int ntp = 0; ntp < 4; ntp++) {
            uint32_t b00, b01, b10, b11;
            ldmatrix_x4(b00, b01, b10, b11, addrB + ntp * 16 * (HP * 2) + koff);
#pragma unroll
            for (int mt = 0; mt < 2; mt++) {
                mma_f16(acc[mt][2 * ntp],     afr[mt][0], afr[mt][1],
                        afr[mt][2], afr[mt][3], b00, b01);
                mma_f16(acc[mt][2 * ntp + 1], afr[mt][0], afr[mt][1],
                        afr[mt][2], afr[mt][3], b10, b11);
            }
        }
    }

#pragma unroll
    for (int nt = 0; nt < 8; nt++) {
        const int c0 = wn + nt * 8 + 2 * tg;
        const int c1 = c0 + 1;
        const float b0 = __ldg(bias + c0);
        const float b1 = __ldg(bias + c1);
        const int p0 = (c0 & 7) * HDIM + (c0 >> 3);   // permuted slot
        const int p1 = (c1 & 7) * HDIM + (c1 >> 3);
#pragma unroll
        for (int mt = 0; mt < 2; mt++) {
            const int r0 = row0 + wm + mt * 16 + group;
            const int r1 = r0 + 8;
            if (r0 < N) {
                if (z == 1) {
                    g_K[(size_t)r0 * H + p0] = __float2half_rn(acc[mt][nt][0] + b0);
                    g_K[(size_t)r0 * H + p1] = __float2half_rn(acc[mt][nt][1] + b1);
                } else {
                    *reinterpret_cast<__half2*>(g_V + (size_t)r0 * H + c0) =
                        __floats2half2_rn(acc[mt][nt][0] + b0, acc[mt][nt][1] + b1);
                }
            }
            if (r1 < N) {
                if (z == 1) {
                    g_K[(size_t)r1 * H + p0] = __float2half_rn(acc[mt][nt][2] + b0);
                    g_K[(size_t)r1 * H + p1] = __float2half_rn(acc[mt][nt][3] + b1);
                } else {
                    *reinterpret_cast<__half2*>(g_V + (size_t)r1 * H + c0) =
                        __floats2half2_rn(acc[mt][nt][2] + b0, acc[mt][nt][3] + b1);
                }
            }
        }
    }
}

// ---------------- merged projection kernel: one 3*391-block launch ----------
__global__ __launch_bounds__(256, 2) void proj_gemm(
    const float* __restrict__ hmat,
    const float* __restrict__ Wq, const float* __restrict__ bq,
    const float* __restrict__ Wk, const float* __restrict__ bk,
    const float* __restrict__ Wv, const float* __restrict__ bv,
    int N)
{
    extern __shared__ __align__(16) char dsm[];
    const int z = blockIdx.z;
    if (z == 0) {
        q_path_ffma(dsm, hmat, Wq, bq, N);
    } else if (z == 1) {
        kv_path_hmma(dsm, hmat, Wk, bk, N, 1);
    } else {
        kv_path_hmma(dsm, hmat, Wv, bv, N, 2);
    }
}

// ---------------- fused sparse attention (exact R12: 46.2us measured) -------
__global__ __launch_bounds__(256) void attn_kernel(
    const int* __restrict__ row_ptr,
    const int* __restrict__ col_ind,
    float* __restrict__ out,
    int N)
{
    __shared__ float att[8][NH][MAXDEG];   // [local warp][head][edge]

    const int wl   = threadIdx.x >> 5;
    const int lane = threadIdx.x & 31;
    const int node = blockIdx.x * 8 + wl;
    if (node >= N) return;

    const int start = row_ptr[node];
    int deg = row_ptr[node + 1] - start;
    if (deg > MAXDEG) deg = MAXDEG;

    int colv = 0;
    if (lane < MAXDEG && lane < deg) colv = col_ind[start + lane];

    const float4 q4 = *reinterpret_cast<const float4*>(g_Q + (size_t)node * H + lane * 4);

    const float NEG_INF = __int_as_float(0xff800000);
    float sc[MAXDEG];
#pragma unroll
    for (int e = 0; e < MAXDEG; e++) {
        int col = __shfl_sync(0xffffffffu, colv, e);
        uint2 kr = __ldg(reinterpret_cast<const uint2*>(g_K + (size_t)col * H) + lane);
        float2 k01 = __half22float2(*reinterpret_cast<const __half2*>(&kr.x));
        float2 k23 = __half22float2(*reinterpret_cast<const __half2*>(&kr.y));
        float p = q4.x * k01.x + q4.y * k01.y + q4.z * k23.x + q4.w * k23.y;
        p += __shfl_xor_sync(0xffffffffu, p, 1);
        p += __shfl_xor_sync(0xffffffffu, p, 2);   // quad = 16 d's of head lane>>2
        sc[e] = (e < deg) ? p : NEG_INF;
    }

    float m = NEG_INF;
#pragma unroll
    for (int e = 0; e < MAXDEG; e++) m = fmaxf(m, sc[e]);
    float s = 0.0f;
#pragma unroll
    for (int e = 0; e < MAXDEG; e++) { float x = __expf(sc[e] - m); sc[e] = x; s += x; }
    float r = __frcp_rn(s);
#pragma unroll
    for (int e = 0; e < MAXDEG; e++) sc[e] *= r;

    {
        int hd = lane >> 2;
        int e0 = (lane & 3) * 4;
        *reinterpret_cast<float4*>(&att[wl][hd][e0]) =
            make_float4(sc[e0], sc[e0 + 1], sc[e0 + 2], sc[e0 + 3]);
    }
    __syncwarp();

    const int base = (lane & 1) * 4;
    float4 acc = make_float4(0.f, 0.f, 0.f, 0.f);
#pragma unroll
    for (int e0 = 0; e0 < MAXDEG; e0 += 4) {
        float4 a0 = *reinterpret_cast<const float4*>(&att[wl][base + 0][e0]);
        float4 a1 = *reinterpret_cast<const float4*>(&att[wl][base + 1][e0]);
        float4 a2 = *reinterpret_cast<const float4*>(&att[wl][base + 2][e0]);
        float4 a3 = *reinterpret_cast<const float4*>(&att[wl][base + 3][e0]);
        const float* w0 = reinterpret_cast<const float*>(&a0);
        const float* w1 = reinterpret_cast<const float*>(&a1);
        const float* w2 = reinterpret_cast<const float*>(&a2);
        const float* w3 = reinterpret_cast<const float*>(&a3);
#pragma unroll
        for (int u = 0; u < 4; u++) {
            int col = __shfl_sync(0xffffffffu, colv, e0 + u);
            uint2 vr = __ldg(reinterpret_cast<const uint2*>(g_V + (size_t)col * H) + lane);
            float2 v01 = __half22float2(*reinterpret_cast<const __half2*>(&vr.x));
            float2 v23 = __half22float2(*reinterpret_cast<const __half2*>(&vr.y));
            acc.x += w0[u] * v01.x;
            acc.y += w1[u] * v01.y;
            acc.z += w2[u] * v23.x;
            acc.w += w3[u] * v23.y;
        }
    }
    *reinterpret_cast<float4*>(out + (size_t)node * H + lane * 4) = acc;
}

// ---------------- launch -----------------------------------------------------
extern "C" void kernel_launch(void* const* d_in, const int* in_sizes, int n_in,
                              void* d_out, int out_size) {
    const float* h   = (const float*)d_in[0];
    const float* Wq  = (const float*)d_in[1];
    const float* bq  = (const float*)d_in[2];
    const float* Wk  = (const float*)d_in[3];
    const float* bk  = (const float*)d_in[4];
    const float* Wv  = (const float*)d_in[5];
    const float* bv  = (const float*)d_in[6];
    const int* row_ptr = (const int*)d_in[7];
    const int* col_ind = (const int*)d_in[8];
    float* out = (float*)d_out;

    const int N = in_sizes[0] / H;
    const int gblocks = (N + 127) / 128;

    static bool attr_set = false;
    if (!attr_set) {
        cudaFuncSetAttribute(proj_gemm,
                             cudaFuncAttributeMaxDynamicSharedMemorySize, PROJ_SMEM);
        attr_set = true;
    }

    proj_gemm<<<dim3(gblocks, 1, 3), 256, PROJ_SMEM>>>(h, Wq, bq, Wk, bk, Wv, bv, N);

    const int ablocks = (N + 7) / 8;
    attn_kernel<<<ablocks, 256>>>(row_ptr, col_ind, out, N);
}